// round 12
// baseline (speedup 1.0000x reference)
#include <cuda_runtime.h>
#include <cuda_bf16.h>
#include <math.h>

// ---------------------------------------------------------------------------
// DRMM matching score, GB300 (sm_103a) — round 12: COALESCED STAGING
//   Diagnosis: every prior kernel staged d-rows as per-thread row reads ->
//   32 L1 wavefronts per LDG (stride 200B). ~50-75us of chip-wide L1 throughput.
//   Fix: coalesced LDG -> smem stage (2 wf/LDG), conflict-free LDS.128 row
//   reads (stride 52 floats), then bf16-split tile build. Stage buffers alias
//   the A/B tile regions (read-all, sync, overwrite).
//   Mainloop/epilogue = round 11 (HMMA nt=7 + nibble/butterfly histogram).
//   g_part int->u8: 4x less reduce traffic.
//   Gating branch dropped: softmax over batch sums to exactly 1.
// ---------------------------------------------------------------------------

#define BB   256
#define QQ   50
#define EE   50
#define DD   2000
#define NB   11
#define QB   (QQ * NB)        // 550
#define MT   128
#define NTILE 16
#define ROWB 336              // bf16 tile row stride bytes
#define KSTEPS 10             // K=160 / 16
#define NT7  7                // q n-tiles (56 >= 50)

#define SM_B    0             // bf16 B tile: 56*336 = 18816 (stage q aliases: 50*208=10400)
#define SM_A    18816         // bf16 A tile: 128*336 = 43008 (stage d aliases: 128*208=26624)
#define SM_HIST 61824         // 550*4 = 2200
#define SM_QV   64024         // 64
#define SM_DV   64088         // 128
#define SM_TOTAL 64256

__device__ unsigned char g_part[(size_t)NTILE * BB * QB];   // u8 slices (counts <= 128)

typedef unsigned long long u64;

__device__ __forceinline__ unsigned smem_u32(const void* p) {
    unsigned a;
    asm("{ .reg .u64 t; cvta.to.shared.u64 t, %1; cvt.u32.u64 %0, t; }"
        : "=r"(a) : "l"(p));
    return a;
}
__device__ __forceinline__ void split2(float x0, float x1,
                                       unsigned& hi, unsigned& lo) {
    __nv_bfloat16 h0 = __float2bfloat16(x0);
    __nv_bfloat16 h1 = __float2bfloat16(x1);
    float r0 = x0 - __bfloat162float(h0);
    float r1 = x1 - __bfloat162float(h1);
    __nv_bfloat16 l0 = __float2bfloat16(r0);
    __nv_bfloat16 l1 = __float2bfloat16(r1);
    hi = (unsigned)__bfloat16_as_ushort(h0) | ((unsigned)__bfloat16_as_ushort(h1) << 16);
    lo = (unsigned)__bfloat16_as_ushort(l0) | ((unsigned)__bfloat16_as_ushort(l1) << 16);
}
__device__ __forceinline__ void ldsm4(unsigned addr, unsigned& r0, unsigned& r1,
                                      unsigned& r2, unsigned& r3) {
    asm volatile("ldmatrix.sync.aligned.m8n8.x4.shared.b16 {%0,%1,%2,%3}, [%4];"
                 : "=r"(r0), "=r"(r1), "=r"(r2), "=r"(r3) : "r"(addr));
}
__device__ __forceinline__ void ldsm2(unsigned addr, unsigned& r0, unsigned& r1) {
    asm volatile("ldmatrix.sync.aligned.m8n8.x2.shared.b16 {%0,%1}, [%2];"
                 : "=r"(r0), "=r"(r1) : "r"(addr));
}
__device__ __forceinline__ void mma16816(float* c, const unsigned* a,
                                         unsigned b0, unsigned b1) {
    asm volatile(
        "mma.sync.aligned.m16n8k16.row.col.f32.bf16.bf16.f32 "
        "{%0,%1,%2,%3}, {%4,%5,%6,%7}, {%8,%9}, {%0,%1,%2,%3};"
        : "+f"(c[0]), "+f"(c[1]), "+f"(c[2]), "+f"(c[3])
        : "r"(a[0]), "r"(a[1]), "r"(a[2]), "r"(a[3]), "r"(b0), "r"(b1));
}

// ---------------------------------------------------------------------------
__global__ void __launch_bounds__(128, 3)
simhist_kernel(const float* __restrict__ qemb,
               const float* __restrict__ demb,
               const int*   __restrict__ qids,
               const int*   __restrict__ dids)
{
    extern __shared__ char smem[];
    const unsigned sbase = smem_u32(smem);
    const int b    = blockIdx.y;
    const int tile = blockIdx.x;
    const int tid  = threadIdx.x;
    const int lane = tid & 31;
    const int w    = tid >> 5;

    int* hist_s = (int*)(smem + SM_HIST);
    unsigned char* qv_s = (unsigned char*)(smem + SM_QV);
    unsigned char* dv_s = (unsigned char*)(smem + SM_DV);

    float2* stA = (float2*)(smem + SM_A);    // stage d rows: stride 26 float2
    float2* stB = (float2*)(smem + SM_B);    // stage q rows: stride 26 float2

    // ==== phase 0: coalesced staging (linear idx == memory order) ====
    {
        const float2* dsrc = (const float2*)(demb + ((size_t)b * DD + tile * MT) * EE);
        const int maxi = (DD - tile * MT) >= MT ? (MT * 25) : (DD - tile * MT) * 25;
#pragma unroll
        for (int it = 0; it < 25; it++) {
            int i = tid + it * 128;                          // i = row*25 + c
            float2 v = (i < maxi) ? dsrc[i] : make_float2(0.f, 0.f);
            stA[(i / 25) * 26 + (i % 25)] = v;
        }
        const float2* qsrc = (const float2*)(qemb + (size_t)b * QQ * EE);
        for (int i = tid; i < QQ * 25; i += 128)
            stB[(i / 25) * 26 + (i % 25)] = qsrc[i];

        for (int i = tid; i < QB; i += 128) hist_s[i] = 0;

        const int gd = tile * MT + tid;
        dv_s[tid] = (gd < DD && dids[b * DD + (gd < DD ? gd : 0)] > 0) ? 1 : 0;
        if (tid < 56)
            qv_s[tid] = (tid < QQ && qids[b * QQ + tid] > 0) ? 1 : 0;
    }
    __syncthreads();

    // ==== phase 1: read own d-row (conflict-free LDS.128), norm ====
    float a[52];
    {
        const float4* row = (const float4*)(stA + (size_t)tid * 26);
#pragma unroll
        for (int j = 0; j < 13; j++) {
            float4 v = row[j];
            a[4 * j] = v.x; a[4 * j + 1] = v.y; a[4 * j + 2] = v.z; a[4 * j + 3] = v.w;
        }
        a[50] = 0.f; a[51] = 0.f;                // pad lanes (stage garbage)
        float ss = 0.f;
#pragma unroll
        for (int e = 0; e < 50; e++) ss += a[e] * a[e];
        const float r = 1.0f / (sqrtf(ss) + 1e-8f);
#pragma unroll
        for (int e = 0; e < 50; e++) a[e] *= r;
    }
    __syncthreads();                              // all stage-A reads done

    // ==== phase 2: write bf16 A tile (overwrites stage-A) ====
    {
        unsigned* arow = (unsigned*)(smem + SM_A + tid * ROWB);
#pragma unroll
        for (int c = 0; c < 25; c++) {
            unsigned hi, lo;
            split2(a[2 * c], a[2 * c + 1], hi, lo);
            arow[c]      = hi;
            arow[25 + c] = hi;
            arow[50 + c] = lo;
        }
#pragma unroll
        for (int j = 75; j < 84; j++) arow[j] = 0;
    }

    // ==== phase 3: q rows (threads 0..55) ====
    float qrow[52];
    if (tid < QQ) {
        const float4* row = (const float4*)(stB + (size_t)tid * 26);
#pragma unroll
        for (int j = 0; j < 13; j++) {
            float4 v = row[j];
            qrow[4 * j] = v.x; qrow[4 * j + 1] = v.y; qrow[4 * j + 2] = v.z; qrow[4 * j + 3] = v.w;
        }
        qrow[50] = 0.f; qrow[51] = 0.f;
        float ss = 0.f;
#pragma unroll
        for (int e = 0; e < 50; e++) ss += qrow[e] * qrow[e];
        const float rq = 1.0f / (sqrtf(ss) + 1e-8f);
#pragma unroll
        for (int e = 0; e < 50; e++) qrow[e] *= rq;
    }
    __syncthreads();                              // stage-B reads done

    if (tid < 56) {
        unsigned* brow = (unsigned*)(smem + SM_B + tid * ROWB);
        if (tid < QQ) {
#pragma unroll
            for (int c = 0; c < 25; c++) {
                unsigned hi, lo;
                split2(qrow[2 * c], qrow[2 * c + 1], hi, lo);
                brow[c]      = hi;
                brow[25 + c] = lo;
                brow[50 + c] = hi;
            }
#pragma unroll
            for (int j = 75; j < 84; j++) brow[j] = 0;
        } else {
#pragma unroll
            for (int j = 0; j < 84; j++) brow[j] = 0;
        }
    }
    __syncthreads();

    // ==== HMMA mainloop (R11: nt=7) ====
    float acc[2][NT7][4];
#pragma unroll
    for (int mt = 0; mt < 2; mt++)
#pragma unroll
        for (int nt = 0; nt < NT7; nt++)
#pragma unroll
            for (int ci = 0; ci < 4; ci++) acc[mt][nt][ci] = 0.f;

    const unsigned aAddr = sbase + SM_A + (unsigned)(w * 32 + (lane & 15)) * ROWB
                         + (unsigned)((lane >> 4) * 16);
    const unsigned bAddr = sbase + SM_B
                         + (unsigned)((lane >> 4) * 8 + (lane & 7)) * ROWB
                         + (unsigned)(((lane >> 3) & 1) * 16);
    const unsigned bAddr2 = sbase + SM_B
                          + (unsigned)(48 + (lane & 7)) * ROWB
                          + (unsigned)(((lane >> 3) & 1) * 16);

#pragma unroll
    for (int ks = 0; ks < KSTEPS; ks++) {
        unsigned am[2][4];
        ldsm4(aAddr + ks * 32,             am[0][0], am[0][1], am[0][2], am[0][3]);
        ldsm4(aAddr + 16 * ROWB + ks * 32, am[1][0], am[1][1], am[1][2], am[1][3]);
        unsigned bq[3][4];
#pragma unroll
        for (int p = 0; p < 3; p++)
            ldsm4(bAddr + (unsigned)(p * 16 * ROWB) + ks * 32,
                  bq[p][0], bq[p][1], bq[p][2], bq[p][3]);
        unsigned b6lo, b6hi;
        ldsm2(bAddr2 + ks * 32, b6lo, b6hi);
#pragma unroll
        for (int mt = 0; mt < 2; mt++) {
#pragma unroll
            for (int p = 0; p < 3; p++) {
                mma16816(acc[mt][2 * p],     am[mt], bq[p][0], bq[p][1]);
                mma16816(acc[mt][2 * p + 1], am[mt], bq[p][2], bq[p][3]);
            }
            mma16816(acc[mt][6], am[mt], b6lo, b6hi);
        }
    }

    // ==== epilogue: nibble hist + butterfly (R7-proven) ====
    const int r0 = w * 32 + (lane >> 2);
    const unsigned dvq = (unsigned)dv_s[r0]
                       | ((unsigned)dv_s[r0 + 8]  << 1)
                       | ((unsigned)dv_s[r0 + 16] << 2)
                       | ((unsigned)dv_s[r0 + 24] << 3);
    const int copyidx = lane >> 2;
    const int cbase   = (lane & 3) * 2;

#pragma unroll
    for (int nt = 0; nt < NT7; nt++) {
#pragma unroll
        for (int half = 0; half < 2; half++) {
            const int q = nt * 8 + cbase + half;
            u64 h = 0ull;
            {
                float s0 = acc[0][nt][half];
                float s1 = acc[0][nt][half + 2];
                float s2 = acc[1][nt][half];
                float s3 = acc[1][nt][half + 2];
                int c0 = min(max((int)fmaf(s0, 5.0f, 5.000005f), 0), NB - 1);
                int c1 = min(max((int)fmaf(s1, 5.0f, 5.000005f), 0), NB - 1);
                int c2 = min(max((int)fmaf(s2, 5.0f, 5.000005f), 0), NB - 1);
                int c3 = min(max((int)fmaf(s3, 5.0f, 5.000005f), 0), NB - 1);
                h += (u64)(dvq & 1u)        << (c0 * 4);
                h += (u64)((dvq >> 1) & 1u) << (c1 * 4);
                h += (u64)((dvq >> 2) & 1u) << (c2 * 4);
                h += (u64)((dvq >> 3) & 1u) << (c3 * 4);
            }
            u64 he = h & 0x0F0F0F0F0F0F0F0Full;
            u64 ho = (h >> 4) & 0x0F0F0F0F0F0F0F0Full;
#pragma unroll
            for (int o = 4; o < 32; o <<= 1) {
                he += __shfl_xor_sync(0xffffffffu, he, o);
                ho += __shfl_xor_sync(0xffffffffu, ho, o);
            }
            if (((nt * 2 + half) & 7) == copyidx && q < QQ && qv_s[q]) {
#pragma unroll
                for (int bin = 0; bin < NB; bin++) {
                    u64 src = (bin & 1) ? ho : he;
                    int cnt = (int)((src >> ((bin >> 1) * 8)) & 0xFFull);
                    if (cnt) atomicAdd(&hist_s[q * NB + bin], cnt);
                }
            }
        }
    }

    __syncthreads();
    unsigned char* dst = g_part + ((size_t)tile * BB + b) * QB;
    for (int i = tid; i < QB; i += 128) dst[i] = (unsigned char)hist_s[i];
}

// ---------------------------------------------------------------------------
__global__ void reduce_kernel(const float* __restrict__ W1,
                              const float* __restrict__ b1,
                              float* __restrict__ out)
{
    const int b = blockIdx.x;
    const int t = threadIdx.x;
    float p = 0.f;
    for (int i = t; i < QB; i += 256) {
        int h = 0;
#pragma unroll
        for (int s = 0; s < NTILE; s++)
            h += g_part[((size_t)s * BB + b) * QB + i];
        p += logf((float)h + 1e-5f) * W1[i];
    }
#pragma unroll
    for (int o = 16; o > 0; o >>= 1) p += __shfl_down_sync(0xffffffffu, p, o);

    __shared__ float red[8];
    if ((t & 31) == 0) red[t >> 5] = p;
    __syncthreads();
    if (t == 0) {
        float s = 0.f;
#pragma unroll
        for (int i = 0; i < 8; i++) s += red[i];
        out[b] = s + b1[0];
    }
}

// ---------------------------------------------------------------------------
extern "C" void kernel_launch(void* const* d_in, const int* in_sizes, int n_in,
                              void* d_out, int out_size)
{
    const float* qemb = (const float*)d_in[0];
    const float* demb = (const float*)d_in[1];
    const float* W1   = (const float*)d_in[2];
    const float* b1   = (const float*)d_in[3];
    const int*   qids = (const int*)d_in[5];
    const int*   dids = (const int*)d_in[6];
    for (int i = 0; i < n_in; i++) {
        switch (in_sizes[i]) {
            case BB * QQ * EE:  qemb = (const float*)d_in[i]; break;
            case BB * DD * EE:  demb = (const float*)d_in[i]; break;
            case QB:            W1   = (const float*)d_in[i]; break;
            case 1:             b1   = (const float*)d_in[i]; break;
            case BB * QQ:       qids = (const int*)d_in[i];   break;
            case BB * DD:       dids = (const int*)d_in[i];   break;
            default: break;     // Wg unused (softmax over batch sums to 1)
        }
    }
    float* out = (float*)d_out;

    static int smem_set = 0;
    if (!smem_set) {
        cudaFuncSetAttribute(simhist_kernel,
                             cudaFuncAttributeMaxDynamicSharedMemorySize, SM_TOTAL);
        smem_set = 1;
    }

    dim3 grid(NTILE, BB);                         // (16, 256) — single launch
    simhist_kernel<<<grid, 128, SM_TOTAL>>>(qemb, demb, qids, dids);
    reduce_kernel<<<BB, 256>>>(W1, b1, out);
}

// round 13
// speedup vs baseline: 1.0547x; 1.0547x over previous
#include <cuda_runtime.h>
#include <cuda_bf16.h>
#include <math.h>

// ---------------------------------------------------------------------------
// DRMM matching score, GB300 (sm_103a) — round 13: R11 + FUSED REDUCTION
//   Single kernel launch (threadfence-reduction: last CTA per batch sums the
//   16 u8 slices, applies log*W1 + b1, writes out[b], resets its ticket).
//   -> removes the reduce launch (~6-7us) AND guarantees ncu captures the
//   main kernel next round (it is the only kernel).
//   Core = round 11 exactly (129.1us best): bf16-split HMMA nt=7 +
//   nibble/butterfly histogram epilogue.
//   Gating branch dropped: softmax over batch sums to exactly 1.
// ---------------------------------------------------------------------------

#define BB   256
#define QQ   50
#define EE   50
#define DD   2000
#define NB   11
#define QB   (QQ * NB)        // 550
#define MT   128
#define NTILE 16
#define ROWB 336              // smem row stride bytes (168 bf16)
#define KSTEPS 10             // K=160 / 16
#define NT7  7                // q n-tiles (56 >= 50)

#define SM_B    0             // 64 * 336  = 21504
#define SM_A    21504         // 128 * 336 = 43008 -> 64512
#define SM_HIST 64512         // 550 * 4            -> 66712
#define SM_QV   66712         // 64 bytes           -> 66776
#define SM_DV   66776         // 128 bytes          -> 66904
#define SM_TOTAL 66944

__device__ unsigned char g_part[(size_t)NTILE * BB * QB];  // u8 slices (counts <= 128)
__device__ int g_done[BB];                                  // tickets (self-resetting)

typedef unsigned long long u64;

__device__ __forceinline__ unsigned smem_u32(const void* p) {
    unsigned a;
    asm("{ .reg .u64 t; cvta.to.shared.u64 t, %1; cvt.u32.u64 %0, t; }"
        : "=r"(a) : "l"(p));
    return a;
}
__device__ __forceinline__ void split2(float x0, float x1,
                                       unsigned& hi, unsigned& lo) {
    __nv_bfloat16 h0 = __float2bfloat16(x0);
    __nv_bfloat16 h1 = __float2bfloat16(x1);
    float r0 = x0 - __bfloat162float(h0);
    float r1 = x1 - __bfloat162float(h1);
    __nv_bfloat16 l0 = __float2bfloat16(r0);
    __nv_bfloat16 l1 = __float2bfloat16(r1);
    hi = (unsigned)__bfloat16_as_ushort(h0) | ((unsigned)__bfloat16_as_ushort(h1) << 16);
    lo = (unsigned)__bfloat16_as_ushort(l0) | ((unsigned)__bfloat16_as_ushort(l1) << 16);
}
__device__ __forceinline__ void ldsm4(unsigned addr, unsigned& r0, unsigned& r1,
                                      unsigned& r2, unsigned& r3) {
    asm volatile("ldmatrix.sync.aligned.m8n8.x4.shared.b16 {%0,%1,%2,%3}, [%4];"
                 : "=r"(r0), "=r"(r1), "=r"(r2), "=r"(r3) : "r"(addr));
}
__device__ __forceinline__ void ldsm2(unsigned addr, unsigned& r0, unsigned& r1) {
    asm volatile("ldmatrix.sync.aligned.m8n8.x2.shared.b16 {%0,%1}, [%2];"
                 : "=r"(r0), "=r"(r1) : "r"(addr));
}
__device__ __forceinline__ void mma16816(float* c, const unsigned* a,
                                         unsigned b0, unsigned b1) {
    asm volatile(
        "mma.sync.aligned.m16n8k16.row.col.f32.bf16.bf16.f32 "
        "{%0,%1,%2,%3}, {%4,%5,%6,%7}, {%8,%9}, {%0,%1,%2,%3};"
        : "+f"(c[0]), "+f"(c[1]), "+f"(c[2]), "+f"(c[3])
        : "r"(a[0]), "r"(a[1]), "r"(a[2]), "r"(a[3]), "r"(b0), "r"(b1));
}

// ---------------------------------------------------------------------------
__global__ void __launch_bounds__(128, 3)
simhist_kernel(const float* __restrict__ qemb,
               const float* __restrict__ demb,
               const int*   __restrict__ qids,
               const int*   __restrict__ dids,
               const float* __restrict__ W1,
               const float* __restrict__ b1,
               float* __restrict__ out)
{
    extern __shared__ char smem[];
    const unsigned sbase = smem_u32(smem);
    const int b    = blockIdx.y;
    const int tile = blockIdx.x;
    const int tid  = threadIdx.x;
    const int lane = tid & 31;
    const int w    = tid >> 5;

    int* hist_s = (int*)(smem + SM_HIST);
    unsigned char* qv_s = (unsigned char*)(smem + SM_QV);
    unsigned char* dv_s = (unsigned char*)(smem + SM_DV);

    for (int i = tid; i < QB; i += 128) hist_s[i] = 0;

    // ---- build B tile (q side): rows 0..55 used ----
    if (tid < 56) {
        unsigned* brow = (unsigned*)(smem + SM_B + tid * ROWB);
        if (tid < QQ) {
            const float2* src = (const float2*)(qemb + ((size_t)b * QQ + tid) * EE);
            float2 v[25];
            float ss = 0.f;
#pragma unroll
            for (int c = 0; c < 25; c++) { v[c] = src[c]; ss += v[c].x * v[c].x + v[c].y * v[c].y; }
            const float r = 1.0f / (sqrtf(ss) + 1e-8f);
            qv_s[tid] = (qids[b * QQ + tid] > 0) ? 1 : 0;
#pragma unroll
            for (int c = 0; c < 25; c++) {
                unsigned hi, lo;
                split2(v[c].x * r, v[c].y * r, hi, lo);
                brow[c]      = hi;
                brow[25 + c] = lo;
                brow[50 + c] = hi;
            }
#pragma unroll
            for (int j = 75; j < 84; j++) brow[j] = 0;
        } else {
            qv_s[tid] = 0;
#pragma unroll
            for (int j = 0; j < 84; j++) brow[j] = 0;
        }
    }

    // ---- build A tile (d side): each thread one row ----
    {
        const int gd  = tile * MT + tid;
        const bool ok = (gd < DD);
        const float2* src = (const float2*)(demb + ((size_t)b * DD + (ok ? gd : 0)) * EE);
        float2 v[25];
        float ss = 0.f;
#pragma unroll
        for (int c = 0; c < 25; c++) {
            float2 x = ok ? src[c] : make_float2(0.f, 0.f);
            v[c] = x;
            ss += x.x * x.x + x.y * x.y;
        }
        const float r = 1.0f / (sqrtf(ss) + 1e-8f);
        dv_s[tid] = (ok && dids[b * DD + (ok ? gd : 0)] > 0) ? 1 : 0;

        unsigned* arow = (unsigned*)(smem + SM_A + tid * ROWB);
#pragma unroll
        for (int c = 0; c < 25; c++) {
            unsigned hi, lo;
            split2(v[c].x * r, v[c].y * r, hi, lo);
            arow[c]      = hi;
            arow[25 + c] = hi;
            arow[50 + c] = lo;
        }
#pragma unroll
        for (int j = 75; j < 84; j++) arow[j] = 0;
    }
    __syncthreads();

    // ---- HMMA mainloop (nt = 7: q-cols 0..55 only) ----
    float acc[2][NT7][4];
#pragma unroll
    for (int mt = 0; mt < 2; mt++)
#pragma unroll
        for (int nt = 0; nt < NT7; nt++)
#pragma unroll
            for (int ci = 0; ci < 4; ci++) acc[mt][nt][ci] = 0.f;

    const unsigned aAddr = sbase + SM_A + (unsigned)(w * 32 + (lane & 15)) * ROWB
                         + (unsigned)((lane >> 4) * 16);
    const unsigned bAddr = sbase + SM_B
                         + (unsigned)((lane >> 4) * 8 + (lane & 7)) * ROWB
                         + (unsigned)(((lane >> 3) & 1) * 16);
    const unsigned bAddr2 = sbase + SM_B
                          + (unsigned)(48 + (lane & 7)) * ROWB
                          + (unsigned)(((lane >> 3) & 1) * 16);

#pragma unroll
    for (int ks = 0; ks < KSTEPS; ks++) {
        unsigned am[2][4];
        ldsm4(aAddr + ks * 32,             am[0][0], am[0][1], am[0][2], am[0][3]);
        ldsm4(aAddr + 16 * ROWB + ks * 32, am[1][0], am[1][1], am[1][2], am[1][3]);
        unsigned bq[3][4];
#pragma unroll
        for (int p = 0; p < 3; p++)
            ldsm4(bAddr + (unsigned)(p * 16 * ROWB) + ks * 32,
                  bq[p][0], bq[p][1], bq[p][2], bq[p][3]);
        unsigned b6lo, b6hi;
        ldsm2(bAddr2 + ks * 32, b6lo, b6hi);
#pragma unroll
        for (int mt = 0; mt < 2; mt++) {
#pragma unroll
            for (int p = 0; p < 3; p++) {
                mma16816(acc[mt][2 * p],     am[mt], bq[p][0], bq[p][1]);
                mma16816(acc[mt][2 * p + 1], am[mt], bq[p][2], bq[p][3]);
            }
            mma16816(acc[mt][6], am[mt], b6lo, b6hi);
        }
    }

    // ---- epilogue: nibble hist + butterfly (proven) ----
    const int r0 = w * 32 + (lane >> 2);
    const unsigned dvq = (unsigned)dv_s[r0]
                       | ((unsigned)dv_s[r0 + 8]  << 1)
                       | ((unsigned)dv_s[r0 + 16] << 2)
                       | ((unsigned)dv_s[r0 + 24] << 3);
    const int copyidx = lane >> 2;
    const int cbase   = (lane & 3) * 2;

#pragma unroll
    for (int nt = 0; nt < NT7; nt++) {
#pragma unroll
        for (int half = 0; half < 2; half++) {
            const int q = nt * 8 + cbase + half;
            u64 h = 0ull;
            {
                float s0 = acc[0][nt][half];
                float s1 = acc[0][nt][half + 2];
                float s2 = acc[1][nt][half];
                float s3 = acc[1][nt][half + 2];
                int c0 = min(max((int)fmaf(s0, 5.0f, 5.000005f), 0), NB - 1);
                int c1 = min(max((int)fmaf(s1, 5.0f, 5.000005f), 0), NB - 1);
                int c2 = min(max((int)fmaf(s2, 5.0f, 5.000005f), 0), NB - 1);
                int c3 = min(max((int)fmaf(s3, 5.0f, 5.000005f), 0), NB - 1);
                h += (u64)(dvq & 1u)        << (c0 * 4);
                h += (u64)((dvq >> 1) & 1u) << (c1 * 4);
                h += (u64)((dvq >> 2) & 1u) << (c2 * 4);
                h += (u64)((dvq >> 3) & 1u) << (c3 * 4);
            }
            u64 he = h & 0x0F0F0F0F0F0F0F0Full;
            u64 ho = (h >> 4) & 0x0F0F0F0F0F0F0F0Full;
#pragma unroll
            for (int o = 4; o < 32; o <<= 1) {
                he += __shfl_xor_sync(0xffffffffu, he, o);
                ho += __shfl_xor_sync(0xffffffffu, ho, o);
            }
            if (((nt * 2 + half) & 7) == copyidx && q < QQ && qv_s[q]) {
#pragma unroll
                for (int bin = 0; bin < NB; bin++) {
                    u64 src = (bin & 1) ? ho : he;
                    int cnt = (int)((src >> ((bin >> 1) * 8)) & 0xFFull);
                    if (cnt) atomicAdd(&hist_s[q * NB + bin], cnt);
                }
            }
        }
    }

    __syncthreads();
    // ---- write u8 slice ----
    unsigned char* dst = g_part + ((size_t)tile * BB + b) * QB;
    for (int i = tid; i < QB; i += 128) dst[i] = (unsigned char)hist_s[i];

    // ---- fused reduction: last CTA for batch b does log*W1+b1 -> out[b] ----
    __threadfence();
    __shared__ int amLast;
    if (tid == 0)
        amLast = (atomicAdd(&g_done[b], 1) == NTILE - 1) ? 1 : 0;
    __syncthreads();
    if (amLast) {
        float p = 0.f;
        for (int i = tid; i < QB; i += 128) {
            int hsum = 0;
#pragma unroll
            for (int s = 0; s < NTILE; s++)
                hsum += (int)g_part[((size_t)s * BB + b) * QB + i];
            p += logf((float)hsum + 1e-5f) * W1[i];
        }
#pragma unroll
        for (int o = 16; o > 0; o >>= 1) p += __shfl_down_sync(0xffffffffu, p, o);
        float* red = (float*)(smem + SM_HIST);     // reuse hist area
        if (lane == 0) red[w] = p;
        __syncthreads();
        if (tid == 0) {
            out[b] = red[0] + red[1] + red[2] + red[3] + b1[0];
            g_done[b] = 0;                          // self-reset for next launch
        }
    }
}

// ---------------------------------------------------------------------------
extern "C" void kernel_launch(void* const* d_in, const int* in_sizes, int n_in,
                              void* d_out, int out_size)
{
    const float* qemb = (const float*)d_in[0];
    const float* demb = (const float*)d_in[1];
    const float* W1   = (const float*)d_in[2];
    const float* b1   = (const float*)d_in[3];
    const int*   qids = (const int*)d_in[5];
    const int*   dids = (const int*)d_in[6];
    for (int i = 0; i < n_in; i++) {
        switch (in_sizes[i]) {
            case BB * QQ * EE:  qemb = (const float*)d_in[i]; break;
            case BB * DD * EE:  demb = (const float*)d_in[i]; break;
            case QB:            W1   = (const float*)d_in[i]; break;
            case 1:             b1   = (const float*)d_in[i]; break;
            case BB * QQ:       qids = (const int*)d_in[i];   break;
            case BB * DD:       dids = (const int*)d_in[i];   break;
            default: break;     // Wg unused (softmax over batch sums to 1)
        }
    }
    float* out = (float*)d_out;

    static int smem_set = 0;
    if (!smem_set) {
        cudaFuncSetAttribute(simhist_kernel,
                             cudaFuncAttributeMaxDynamicSharedMemorySize, SM_TOTAL);
        smem_set = 1;
    }

    dim3 grid(NTILE, BB);                         // (16, 256) — SINGLE launch
    simhist_kernel<<<grid, 128, SM_TOTAL>>>(qemb, demb, qids, dids, W1, b1, out);
}